// round 11
// baseline (speedup 1.0000x reference)
#include <cuda_runtime.h>
#include <cuda_fp16.h>
#include <stdint.h>
#include <math.h>

#define N_PTS 32768
#define DIM   512
#define KCL   1024

// ---------------- scratch (static device arrays: allocation-free) ----------
__device__ __half g_Ah[(size_t)N_PTS * DIM];   // 32 MB  fp16 hi
__device__ __half g_Al[(size_t)N_PTS * DIM];   // 32 MB  fp16 lo (residual)
__device__ __half g_Bh[(size_t)KCL * DIM];     // 1 MB
__device__ __half g_Bl[(size_t)KCL * DIM];     // 1 MB
__device__ float g_xnorm[N_PTS];
__device__ float g_cnorm[KCL];
// per-quarter softmax/argmin partials
__device__ float g_qm[4][N_PTS];
__device__ float g_ql[4][N_PTS];
__device__ float g_qs[4][N_PTS];
__device__ int   g_qi[4][N_PTS];
// per-merge-block loss partials
#define NMERGE 2048
__device__ float g_lpart[NMERGE];

// m16n8k16 fp16 MMA, fp32 accumulate, D=C
#define MMA_F16(d, a, b)                                                        \
    asm volatile(                                                               \
        "mma.sync.aligned.m16n8k16.row.col.f32.f16.f16.f32 "                    \
        "{%0,%1,%2,%3},{%4,%5,%6,%7},{%8,%9},{%0,%1,%2,%3};"                    \
        : "+f"((d)[0]), "+f"((d)[1]), "+f"((d)[2]), "+f"((d)[3])                \
        : "r"((a)[0]), "r"((a)[1]), "r"((a)[2]), "r"((a)[3]),                   \
          "r"((b)[0]), "r"((b)[1]))

// m16n8k16 fp16 MMA, fp16 accumulate (D,C = 2 x u32 = 4 halves), D=C
#define MMA_F16C(d, a, b)                                                       \
    asm volatile(                                                               \
        "mma.sync.aligned.m16n8k16.row.col.f16.f16.f16.f16 "                    \
        "{%0,%1},{%2,%3,%4,%5},{%6,%7},{%0,%1};"                                \
        : "+r"((d)[0]), "+r"((d)[1])                                            \
        : "r"((a)[0]), "r"((a)[1]), "r"((a)[2]), "r"((a)[3]),                   \
          "r"((b)[0]), "r"((b)[1]))

#define LDMX4(r0, r1, r2, r3, addr)                                             \
    asm volatile("ldmatrix.sync.aligned.m8n8.x4.shared.b16 {%0,%1,%2,%3}, [%4];"\
                 : "=r"(r0), "=r"(r1), "=r"(r2), "=r"(r3) : "r"(addr))

#define CP_ASYNC16(dst, src)                                                    \
    asm volatile("cp.async.cg.shared.global [%0], [%1], 16;"                    \
                 :: "r"(dst), "l"(src) : "memory")
#define CP_COMMIT()  asm volatile("cp.async.commit_group;" ::: "memory")
#define CP_WAIT(n)   asm volatile("cp.async.wait_group %0;" :: "n"(n) : "memory")

#define SWZ(x) ((x) ^ (((x) >> 3) & 0x70))

__device__ __forceinline__ uint32_t smem_u32(const void* p) {
    uint32_t a;
    asm("{ .reg .u64 t; cvta.to.shared.u64 t, %1; cvt.u32.u64 %0, t; }" : "=r"(a) : "l"(p));
    return a;
}

// ---------------------------------------------------------------------------
// Convert fp32 rows -> fp16 (hi, lo) split + squared norms.
// One warp per row; rows [0, N_PTS) = input->A, [N_PTS, N_PTS+KCL) = crep->B.
// ---------------------------------------------------------------------------
__global__ void convert_f16_kernel(const float* __restrict__ input,
                                   const float* __restrict__ crep) {
    int warp = (blockIdx.x * blockDim.x + threadIdx.x) >> 5;
    int lane = threadIdx.x & 31;
    if (warp >= N_PTS + KCL) return;
    const int isB = (warp >= N_PTS);
    const int r   = isB ? warp - N_PTS : warp;
    const float* row = (isB ? crep : input) + (size_t)r * DIM;
    __half* hrow = (isB ? g_Bh : g_Ah) + (size_t)r * DIM;
    __half* lrow = (isB ? g_Bl : g_Al) + (size_t)r * DIM;
    float sq = 0.f;
    #pragma unroll
    for (int i = 0; i < 4; i++) {
        int d = i * 128 + lane * 4;
        float4 v = *reinterpret_cast<const float4*>(row + d);
        float vv[4] = {v.x, v.y, v.z, v.w};
        __half hv[4], lv[4];
        #pragma unroll
        for (int q = 0; q < 4; q++) {
            float val = vv[q];
            sq = fmaf(val, val, sq);
            hv[q] = __float2half_rn(val);
            lv[q] = __float2half_rn(val - __half2float(hv[q]));
        }
        *reinterpret_cast<uint2*>(hrow + d) = *reinterpret_cast<uint2*>(hv);
        *reinterpret_cast<uint2*>(lrow + d) = *reinterpret_cast<uint2*>(lv);
    }
    #pragma unroll
    for (int o = 16; o > 0; o >>= 1) sq += __shfl_xor_sync(0xffffffffu, sq, o);
    if (lane == 0) {
        if (isB) g_cnorm[r] = sq;
        else     g_xnorm[r] = sq;
    }
}

// ---------------------------------------------------------------------------
// GEMM kernel: one CTA = M-tile 128 x N-quarter 256, full K. grid = 1024.
// hh pass: fp32-accum MMA. mh+hm correction passes: fp16-accum MMA chained
// into a transient 2-reg fragment, drained to the fp32 accumulators per k16.
// 3-stage cp.async pipeline, ldmatrix fragments, SW128 swizzle.
// ---------------------------------------------------------------------------
#define STG_A   16384              // 128 rows * 128B
#define STG_B   32768              // 256 rows * 128B
#define STG_SZ  (STG_A + STG_B)    // 49152
#define NSTG    16                 // K = 512 / k32
#define DSMEM   (3 * STG_SZ)       // 147456

__global__ __launch_bounds__(256, 1)
void dkm_gemm_kernel()
{
    extern __shared__ __align__(128) char dsm[];
    __shared__ float s_cn[256];
    __shared__ float s_xn[128];
    __shared__ float s_pm[4][128], s_pl[4][128], s_ps[4][128];
    __shared__ int   s_pi[4][128];

    const int tid  = threadIdx.x;
    const int wid  = tid >> 5;
    const int lane = tid & 31;
    const int q    = lane >> 2;
    const int kl   = lane & 3;
    const int g    = lane >> 3;        // ldmatrix address group
    const int lr   = lane & 7;
    const int wm   = wid & 1;          // M-tile (0..1) of 64 rows
    const int wn   = wid >> 1;         // N-tile (0..3) of 64 cols
    const int mt   = blockIdx.x >> 2;  // M-tile index (quarter fastest: A L2 reuse)
    const int qt   = blockIdx.x & 3;   // N-quarter
    const int row0 = mt * 128;
    const int c0   = qt * 256;
    const uint32_t dsmu = smem_u32(dsm);

    s_cn[tid] = g_cnorm[c0 + tid];
    if (tid < 128) s_xn[tid] = g_xnorm[row0 + tid];

    // ---- per-lane ldmatrix offsets (stage-independent) --------------------
    uint32_t offA[4], offB[4];
    #pragma unroll
    for (int mf = 0; mf < 4; mf++) {
        int r = wm * 64 + mf * 16 + (g & 1) * 8 + lr;
        offA[mf] = (uint32_t)(r * 128) + ((uint32_t)((g >> 1) * 16) ^ ((uint32_t)(r & 7) << 4));
    }
    #pragma unroll
    for (int t = 0; t < 4; t++) {
        int r = wn * 64 + t * 16 + (g >= 2 ? 8 : 0) + lr;
        offB[t] = (uint32_t)(r * 128) + ((uint32_t)((g & 1) * 16) ^ ((uint32_t)(r & 7) << 4));
    }

    // ---- stage loader: 3072 x 16B chunks, 12 per thread -------------------
    auto load_stage = [&](int s) {
        const int k0 = s * 32;
        const uint32_t base = dsmu + (s % 3) * STG_SZ;
        #pragma unroll
        for (int it = 0; it < 12; it++) {
            int i = it * 256 + tid;
            uint32_t dst; const __half* src;
            if (i < 1024) {                       // A: 128 rows x 8 chunks
                int r = i >> 3, c = i & 7;
                src = (c < 4 ? g_Ah + (size_t)(row0 + r) * DIM + k0 + c * 8
                             : g_Al + (size_t)(row0 + r) * DIM + k0 + (c - 4) * 8);
                dst = base + SWZ((uint32_t)(r * 128 + c * 16));
            } else {                              // B: 256 rows x 8 chunks
                int j = i - 1024, r = j >> 3, c = j & 7;
                src = (c < 4 ? g_Bh + (size_t)(c0 + r) * DIM + k0 + c * 8
                             : g_Bl + (size_t)(c0 + r) * DIM + k0 + (c - 4) * 8);
                dst = base + STG_A + SWZ((uint32_t)(r * 128 + c * 16));
            }
            CP_ASYNC16(dst, (const void*)src);
        }
        CP_COMMIT();
    };

    float acc[4][8][4];
    #pragma unroll
    for (int mf = 0; mf < 4; mf++)
        #pragma unroll
        for (int nf = 0; nf < 8; nf++)
            #pragma unroll
            for (int t = 0; t < 4; t++) acc[mf][nf][t] = 0.f;

    load_stage(0);
    load_stage(1);

    for (int s = 0; s < NSTG; s++) {
        if (s < NSTG - 2) { CP_WAIT(1); } else { CP_WAIT(0); }
        __syncthreads();
        if (s + 2 < NSTG) load_stage(s + 2);   // overlaps with compute below

        const uint32_t abase = dsmu + (s % 3) * STG_SZ;
        const uint32_t bbase = abase + STG_A;

        #pragma unroll
        for (int kb = 0; kb < 2; kb++) {           // two k16 steps per stage
            const uint32_t kx = (uint32_t)kb << 5;
            uint32_t ah[4][4], am[4][4], bh[4][4];
            #pragma unroll
            for (int mf = 0; mf < 4; mf++) {
                const uint32_t aH = abase + (offA[mf] ^ kx);
                LDMX4(ah[mf][0], ah[mf][1], ah[mf][2], ah[mf][3], aH);
                LDMX4(am[mf][0], am[mf][1], am[mf][2], am[mf][3], aH ^ 64u);
            }
            #pragma unroll
            for (int t = 0; t < 4; t++)
                LDMX4(bh[t][0], bh[t][1], bh[t][2], bh[t][3], bbase + (offB[t] ^ kx));

            #pragma unroll
            for (int t = 0; t < 4; t++) {
                uint32_t bl[4];
                LDMX4(bl[0], bl[1], bl[2], bl[3], bbase + ((offB[t] ^ kx) ^ 64u));
                #pragma unroll
                for (int mf = 0; mf < 4; mf++) {
                    #pragma unroll
                    for (int sub = 0; sub < 2; sub++) {
                        float* af = acc[mf][2 * t + sub];
                        // fp16-accum correction chain: am*bh + ah*bl
                        uint32_t c[2] = {0u, 0u};
                        MMA_F16C(c, am[mf], (bh[t] + 2 * sub));
                        MMA_F16C(c, ah[mf], (bl + 2 * sub));
                        // fp32-accum hh pass (keeps tensor pipe busy over drain)
                        MMA_F16(af, ah[mf], (bh[t] + 2 * sub));
                        // drain correction into fp32 accumulators
                        float2 f0 = __half22float2(*reinterpret_cast<__half2*>(&c[0]));
                        float2 f1 = __half22float2(*reinterpret_cast<__half2*>(&c[1]));
                        af[0] += f0.x; af[1] += f0.y;
                        af[2] += f1.x; af[3] += f1.y;
                    }
                }
            }
        }
    }

    // ---- single epilogue: softmax/argmin over this quarter ----------------
    #pragma unroll
    for (int mf = 0; mf < 4; mf++) {
        #pragma unroll
        for (int j = 0; j < 2; j++) {
            const int rloc = wm * 64 + mf * 16 + j * 8 + q;
            const float xn = s_xn[rloc];
            float d2v[16];
            float bmn = 3.4e38f; int ba = 0;
            #pragma unroll
            for (int nf = 0; nf < 8; nf++) {
                #pragma unroll
                for (int t = 0; t < 2; t++) {
                    int col = c0 + wn * 64 + nf * 8 + 2 * kl + t;
                    float d2 = xn + s_cn[col - c0] - 2.f * acc[mf][nf][j * 2 + t];
                    d2v[nf * 2 + t] = d2;
                    if (d2 < bmn || (d2 == bmn && col < ba)) { bmn = d2; ba = col; }
                }
            }
            #pragma unroll
            for (int o = 1; o <= 2; o <<= 1) {
                float om = __shfl_xor_sync(0xffffffffu, bmn, o);
                int   oa = __shfl_xor_sync(0xffffffffu, ba, o);
                if (om < bmn || (om == bmn && oa < ba)) { bmn = om; ba = oa; }
            }
            float le = 0.f, se = 0.f;
            #pragma unroll
            for (int v = 0; v < 16; v++) {
                float w = __expf(bmn - d2v[v]);
                le += w;
                se = fmaf(w, d2v[v], se);
            }
            #pragma unroll
            for (int o = 1; o <= 2; o <<= 1) {
                le += __shfl_xor_sync(0xffffffffu, le, o);
                se += __shfl_xor_sync(0xffffffffu, se, o);
            }
            if (kl == 0) {
                s_pm[wn][rloc] = bmn;
                s_pl[wn][rloc] = le;
                s_ps[wn][rloc] = se;
                s_pi[wn][rloc] = ba;
            }
        }
    }
    __syncthreads();

    // ---- merge the 4 N-warp partials; write per-quarter global partial ----
    if (tid < 128) {
        float m = s_pm[0][tid]; int bi = s_pi[0][tid];
        #pragma unroll
        for (int w = 1; w < 4; w++) {
            float om = s_pm[w][tid]; int oi = s_pi[w][tid];
            if (om < m || (om == m && oi < bi)) { m = om; bi = oi; }
        }
        float l = 0.f, ssum = 0.f;
        #pragma unroll
        for (int w = 0; w < 4; w++) {
            float sc = __expf(m - s_pm[w][tid]);
            l    += s_pl[w][tid] * sc;
            ssum += s_ps[w][tid] * sc;
        }
        int n = row0 + tid;
        g_qm[qt][n] = m;
        g_ql[qt][n] = l;
        g_qs[qt][n] = ssum;
        g_qi[qt][n] = bi;
    }
}

// ---------------------------------------------------------------------------
// Merge the 4 quarter-partials; idx + loss partial + centroid gather.
// 16 points per block (grid 2048, 256 threads) for high occupancy.
// ---------------------------------------------------------------------------
__global__ __launch_bounds__(256)
void dkm_merge_kernel(const float* __restrict__ crep,
                      float* __restrict__ out_centroids,
                      float* __restrict__ out_idx)
{
    __shared__ int   s_idx[16];
    __shared__ float s_loss[16];
    const int tid = threadIdx.x;
    const int p0  = blockIdx.x * 16;

    if (tid < 16) {
        int n = p0 + tid;
        float m = g_qm[0][n]; int bi = g_qi[0][n];
        #pragma unroll
        for (int qq = 1; qq < 4; qq++) {
            float om = g_qm[qq][n];
            if (om < m) { m = om; bi = g_qi[qq][n]; }
        }
        float l = 0.f, ssum = 0.f;
        #pragma unroll
        for (int qq = 0; qq < 4; qq++) {
            float sc = __expf(m - g_qm[qq][n]);
            l    += g_ql[qq][n] * sc;
            ssum += g_qs[qq][n] * sc;
        }
        out_idx[n]  = (float)bi;
        s_idx[tid]  = bi;
        s_loss[tid] = ssum / l;
    }
    __syncthreads();
    if (tid == 0) {
        float a = 0.f;
        #pragma unroll
        for (int i = 0; i < 16; i++) a += s_loss[i];   // fixed order: deterministic
        g_lpart[blockIdx.x] = a;
    }

    // gather: 16 rows x 128 float4 = 2048 vec ops, 8 per thread
    for (int i = tid; i < 16 * (DIM / 4); i += 256) {
        int p = i >> 7, c4 = i & 127;
        int ci = s_idx[p];
        float4 v = *reinterpret_cast<const float4*>(crep + (size_t)ci * DIM + c4 * 4);
        *reinterpret_cast<float4*>(out_centroids + (size_t)(p0 + p) * DIM + c4 * 4) = v;
    }
}

// ---------------------------------------------------------------------------
// Final deterministic loss: fixed-order tree over the 2048 merge partials.
// ---------------------------------------------------------------------------
__global__ void loss_final_kernel(float* __restrict__ out_loss) {
    __shared__ float sm[1024];
    int tid = threadIdx.x;
    sm[tid] = g_lpart[tid] + g_lpart[tid + 1024];
    __syncthreads();
    #pragma unroll
    for (int o = 512; o > 0; o >>= 1) {
        if (tid < o) sm[tid] += sm[tid + o];
        __syncthreads();
    }
    if (tid == 0) out_loss[0] = sm[0] * (1.0f / (float)KCL);
}

// ---------------------------------------------------------------------------
extern "C" void kernel_launch(void* const* d_in, const int* in_sizes, int n_in,
                              void* d_out, int out_size) {
    const float* input = (const float*)d_in[0];   // [N, D]
    const float* crep  = (const float*)d_in[1];   // [K, D]

    float* out           = (float*)d_out;
    float* out_centroids = out;
    float* out_idx       = out + (size_t)N_PTS * DIM;
    float* out_loss      = out + (size_t)N_PTS * DIM + N_PTS;

    convert_f16_kernel<<<((N_PTS + KCL) * 32) / 256, 256>>>(input, crep);

    cudaFuncSetAttribute(dkm_gemm_kernel, cudaFuncAttributeMaxDynamicSharedMemorySize, DSMEM);
    dkm_gemm_kernel<<<(N_PTS / 128) * 4, 256, DSMEM>>>();

    dkm_merge_kernel<<<NMERGE, 256>>>(crep, out_centroids, out_idx);

    loss_final_kernel<<<1, 1024>>>(out_loss);
}

// round 12
// speedup vs baseline: 1.1928x; 1.1928x over previous
#include <cuda_runtime.h>
#include <cuda_fp16.h>
#include <stdint.h>
#include <math.h>

#define N_PTS 32768
#define DIM   512
#define KCL   1024

// ---------------- scratch (static device arrays: allocation-free) ----------
__device__ __half g_Bh[(size_t)KCL * DIM];     // 1 MB
__device__ __half g_Bl[(size_t)KCL * DIM];     // 1 MB
__device__ float g_cnorm[KCL];
// per-quarter softmax/argmin partials
__device__ float g_qm[4][N_PTS];
__device__ float g_ql[4][N_PTS];
__device__ float g_qs[4][N_PTS];
__device__ int   g_qi[4][N_PTS];
// per-merge-block loss partials
#define NMERGE 2048
__device__ float g_lpart[NMERGE];

// m16n8k16 fp16 MMA, fp32 accumulate, D=C
#define MMA_F16(d, a, b)                                                        \
    asm volatile(                                                               \
        "mma.sync.aligned.m16n8k16.row.col.f32.f16.f16.f32 "                    \
        "{%0,%1,%2,%3},{%4,%5,%6,%7},{%8,%9},{%0,%1,%2,%3};"                    \
        : "+f"((d)[0]), "+f"((d)[1]), "+f"((d)[2]), "+f"((d)[3])                \
        : "r"((a)[0]), "r"((a)[1]), "r"((a)[2]), "r"((a)[3]),                   \
          "r"((b)[0]), "r"((b)[1]))

#define LDMX4(r0, r1, r2, r3, addr)                                             \
    asm volatile("ldmatrix.sync.aligned.m8n8.x4.shared.b16 {%0,%1,%2,%3}, [%4];"\
                 : "=r"(r0), "=r"(r1), "=r"(r2), "=r"(r3) : "r"(addr))

#define CP_ASYNC16(dst, src)                                                    \
    asm volatile("cp.async.cg.shared.global [%0], [%1], 16;"                    \
                 :: "r"(dst), "l"(src) : "memory")
#define CP_COMMIT()  asm volatile("cp.async.commit_group;" ::: "memory")
#define CP_WAIT(n)   asm volatile("cp.async.wait_group %0;" :: "n"(n) : "memory")

#define SWZ(x) ((x) ^ (((x) >> 3) & 0x70))

__device__ __forceinline__ uint32_t smem_u32(const void* p) {
    uint32_t a;
    asm("{ .reg .u64 t; cvta.to.shared.u64 t, %1; cvt.u32.u64 %0, t; }" : "=r"(a) : "l"(p));
    return a;
}

// ---------------------------------------------------------------------------
// Convert crep fp32 rows -> fp16 (hi, lo) split + squared norms. Warp/row.
// (A is now split on-the-fly inside the GEMM kernel.)
// ---------------------------------------------------------------------------
__global__ void convert_b_kernel(const float* __restrict__ crep) {
    int warp = (blockIdx.x * blockDim.x + threadIdx.x) >> 5;
    int lane = threadIdx.x & 31;
    if (warp >= KCL) return;
    const float* row = crep + (size_t)warp * DIM;
    __half* hrow = g_Bh + (size_t)warp * DIM;
    __half* lrow = g_Bl + (size_t)warp * DIM;
    float sq = 0.f;
    #pragma unroll
    for (int i = 0; i < 4; i++) {
        int d = i * 128 + lane * 4;
        float4 v = *reinterpret_cast<const float4*>(row + d);
        float vv[4] = {v.x, v.y, v.z, v.w};
        __half hv[4], lv[4];
        #pragma unroll
        for (int q = 0; q < 4; q++) {
            float val = vv[q];
            sq = fmaf(val, val, sq);
            hv[q] = __float2half_rn(val);
            lv[q] = __float2half_rn(val - __half2float(hv[q]));
        }
        *reinterpret_cast<uint2*>(hrow + d) = *reinterpret_cast<uint2*>(hv);
        *reinterpret_cast<uint2*>(lrow + d) = *reinterpret_cast<uint2*>(lv);
    }
    #pragma unroll
    for (int o = 16; o > 0; o >>= 1) sq += __shfl_xor_sync(0xffffffffu, sq, o);
    if (lane == 0) g_cnorm[warp] = sq;
}

// ---------------------------------------------------------------------------
// GEMM kernel: one CTA = M-tile 128 x N-quarter 256, full K. grid = 1024.
// 3xFP16 mma.sync (hh+mh+hm), ldmatrix fragments, SW128 swizzle.
// B: 3-stage cp.async ring. A: fp32 loaded direct from input, split to
// hi/lo fp16 in registers (one stage ahead), stored to smem; row norms
// accumulated on the fly. Per-quarter partials to global.
// ---------------------------------------------------------------------------
#define STG_A   16384              // 128 rows * 128B
#define STG_B   32768              // 256 rows * 128B
#define STG_SZ  (STG_A + STG_B)    // 49152
#define NSTG    16                 // K = 512 / k32
#define DSMEM   (3 * STG_SZ)       // 147456

__global__ __launch_bounds__(256, 1)
void dkm_gemm_kernel(const float* __restrict__ input)
{
    extern __shared__ __align__(128) char dsm[];
    __shared__ float s_cn[256];
    __shared__ float s_xn[128];
    __shared__ float s_pm[4][128], s_pl[4][128], s_ps[4][128];
    __shared__ int   s_pi[4][128];

    const int tid  = threadIdx.x;
    const int wid  = tid >> 5;
    const int lane = tid & 31;
    const int q    = lane >> 2;
    const int kl   = lane & 3;
    const int g    = lane >> 3;        // ldmatrix address group
    const int lr   = lane & 7;
    const int wm   = wid & 1;          // M-tile (0..1) of 64 rows
    const int wn   = wid >> 1;         // N-tile (0..3) of 64 cols
    const int mt   = blockIdx.x >> 2;  // M-tile index (quarter fastest: A L2 reuse)
    const int qt   = blockIdx.x & 3;   // N-quarter
    const int row0 = mt * 128;
    const int c0   = qt * 256;
    const uint32_t dsmu = smem_u32(dsm);

    s_cn[tid] = g_cnorm[c0 + tid];

    // A loader thread mapping (fixed across stages): 4 chunks per thread
    const int ar = tid >> 3;           // row within block of 32 (offset it*32)
    const int ac = tid & 7;            // 4-float chunk (cols ac*4 .. ac*4+3)

    // ---- per-lane ldmatrix offsets (stage-independent) --------------------
    uint32_t offA[4], offB[4];
    #pragma unroll
    for (int mf = 0; mf < 4; mf++) {
        int r = wm * 64 + mf * 16 + (g & 1) * 8 + lr;
        offA[mf] = (uint32_t)(r * 128) + ((uint32_t)((g >> 1) * 16) ^ ((uint32_t)(r & 7) << 4));
    }
    #pragma unroll
    for (int t = 0; t < 4; t++) {
        int r = wn * 64 + t * 16 + (g >= 2 ? 8 : 0) + lr;
        offB[t] = (uint32_t)(r * 128) + ((uint32_t)((g & 1) * 16) ^ ((uint32_t)(r & 7) << 4));
    }

    // ---- B stage loader: 2048 x 16B chunks, 8 per thread ------------------
    auto load_B = [&](int s) {
        const int k0 = s * 32;
        const uint32_t base = dsmu + (s % 3) * STG_SZ + STG_A;
        #pragma unroll
        for (int it = 0; it < 8; it++) {
            int i = it * 256 + tid;
            int r = i >> 3, c = i & 7;
            const __half* src =
                (c < 4 ? g_Bh + (size_t)(c0 + r) * DIM + k0 + c * 8
                       : g_Bl + (size_t)(c0 + r) * DIM + k0 + (c - 4) * 8);
            CP_ASYNC16(base + SWZ((uint32_t)(r * 128 + c * 16)), (const void*)src);
        }
        CP_COMMIT();
    };

    // ---- A: fp32 prefetch (one stage ahead) + convert/store ---------------
    float4 aPre[4];
    float  ns[4] = {0.f, 0.f, 0.f, 0.f};
    auto load_A = [&](int s) {
        const int k0 = s * 32;
        #pragma unroll
        for (int it = 0; it < 4; it++) {
            int r = it * 32 + ar;
            aPre[it] = *reinterpret_cast<const float4*>(
                &input[(size_t)(row0 + r) * DIM + k0 + ac * 4]);
        }
    };
    auto store_A = [&](int s) {
        const int sb = (s % 3) * STG_SZ;
        #pragma unroll
        for (int it = 0; it < 4; it++) {
            int r = it * 32 + ar;
            float v[4] = {aPre[it].x, aPre[it].y, aPre[it].z, aPre[it].w};
            __half hv[4], lv[4];
            #pragma unroll
            for (int u = 0; u < 4; u++) {
                ns[it] = fmaf(v[u], v[u], ns[it]);
                hv[u] = __float2half_rn(v[u]);
                lv[u] = __float2half_rn(v[u] - __half2float(hv[u]));
            }
            *reinterpret_cast<uint2*>(dsm + sb + SWZ((uint32_t)(r * 128 + ac * 8))) =
                *reinterpret_cast<uint2*>(hv);
            *reinterpret_cast<uint2*>(dsm + sb + SWZ((uint32_t)(r * 128 + 64 + ac * 8))) =
                *reinterpret_cast<uint2*>(lv);
        }
    };

    float acc[4][8][4];
    #pragma unroll
    for (int mf = 0; mf < 4; mf++)
        #pragma unroll
        for (int nf = 0; nf < 8; nf++)
            #pragma unroll
            for (int t = 0; t < 4; t++) acc[mf][nf][t] = 0.f;

    load_B(0);
    load_B(1);
    load_A(0);

    for (int s = 0; s < NSTG; s++) {
        if (s < NSTG - 2) { CP_WAIT(1); } else { CP_WAIT(0); }
        store_A(s);                       // stage-s A region: last read at s-3
        __syncthreads();
        if (s + 2 < NSTG) load_B(s + 2);  // overlaps with compute below
        if (s + 1 < NSTG) load_A(s + 1);

        const uint32_t abase = dsmu + (s % 3) * STG_SZ;
        const uint32_t bbase = abase + STG_A;

        #pragma unroll
        for (int kb = 0; kb < 2; kb++) {           // two k16 steps per stage
            const uint32_t kx = (uint32_t)kb << 5;
            uint32_t ah[4][4], am[4][4], bb[4][4];
            #pragma unroll
            for (int mf = 0; mf < 4; mf++) {
                const uint32_t aH = abase + (offA[mf] ^ kx);
                LDMX4(ah[mf][0], ah[mf][1], ah[mf][2], ah[mf][3], aH);
                LDMX4(am[mf][0], am[mf][1], am[mf][2], am[mf][3], aH ^ 64u);
            }
            // B hi fragments -> passes hh and mh
            #pragma unroll
            for (int t = 0; t < 4; t++)
                LDMX4(bb[t][0], bb[t][1], bb[t][2], bb[t][3], bbase + (offB[t] ^ kx));
            #pragma unroll
            for (int mf = 0; mf < 4; mf++)
                #pragma unroll
                for (int t = 0; t < 4; t++) {
                    MMA_F16(acc[mf][2 * t],     ah[mf], (bb[t] + 0));
                    MMA_F16(acc[mf][2 * t + 1], ah[mf], (bb[t] + 2));
                }
            #pragma unroll
            for (int mf = 0; mf < 4; mf++)
                #pragma unroll
                for (int t = 0; t < 4; t++) {
                    MMA_F16(acc[mf][2 * t],     am[mf], (bb[t] + 0));
                    MMA_F16(acc[mf][2 * t + 1], am[mf], (bb[t] + 2));
                }
            // B lo fragments -> pass hm
            #pragma unroll
            for (int t = 0; t < 4; t++)
                LDMX4(bb[t][0], bb[t][1], bb[t][2], bb[t][3], bbase + ((offB[t] ^ kx) ^ 64u));
            #pragma unroll
            for (int mf = 0; mf < 4; mf++)
                #pragma unroll
                for (int t = 0; t < 4; t++) {
                    MMA_F16(acc[mf][2 * t],     ah[mf], (bb[t] + 0));
                    MMA_F16(acc[mf][2 * t + 1], ah[mf], (bb[t] + 2));
                }
        }
    }

    // ---- publish row norms (8 threads share each row) ---------------------
    #pragma unroll
    for (int it = 0; it < 4; it++) {
        float v = ns[it];
        v += __shfl_xor_sync(0xffffffffu, v, 1);
        v += __shfl_xor_sync(0xffffffffu, v, 2);
        v += __shfl_xor_sync(0xffffffffu, v, 4);
        if ((tid & 7) == 0) s_xn[it * 32 + ar] = v;
    }
    __syncthreads();

    // ---- single epilogue: softmax/argmin over this quarter ----------------
    #pragma unroll
    for (int mf = 0; mf < 4; mf++) {
        #pragma unroll
        for (int j = 0; j < 2; j++) {
            const int rloc = wm * 64 + mf * 16 + j * 8 + q;
            const float xn = s_xn[rloc];
            float d2v[16];
            float bmn = 3.4e38f; int ba = 0;
            #pragma unroll
            for (int nf = 0; nf < 8; nf++) {
                #pragma unroll
                for (int t = 0; t < 2; t++) {
                    int col = c0 + wn * 64 + nf * 8 + 2 * kl + t;
                    float d2 = xn + s_cn[col - c0] - 2.f * acc[mf][nf][j * 2 + t];
                    d2v[nf * 2 + t] = d2;
                    if (d2 < bmn || (d2 == bmn && col < ba)) { bmn = d2; ba = col; }
                }
            }
            #pragma unroll
            for (int o = 1; o <= 2; o <<= 1) {
                float om = __shfl_xor_sync(0xffffffffu, bmn, o);
                int   oa = __shfl_xor_sync(0xffffffffu, ba, o);
                if (om < bmn || (om == bmn && oa < ba)) { bmn = om; ba = oa; }
            }
            float le = 0.f, se = 0.f;
            #pragma unroll
            for (int v = 0; v < 16; v++) {
                float w = __expf(bmn - d2v[v]);
                le += w;
                se = fmaf(w, d2v[v], se);
            }
            #pragma unroll
            for (int o = 1; o <= 2; o <<= 1) {
                le += __shfl_xor_sync(0xffffffffu, le, o);
                se += __shfl_xor_sync(0xffffffffu, se, o);
            }
            if (kl == 0) {
                s_pm[wn][rloc] = bmn;
                s_pl[wn][rloc] = le;
                s_ps[wn][rloc] = se;
                s_pi[wn][rloc] = ba;
            }
        }
    }
    __syncthreads();

    // ---- merge the 4 N-warp partials; write per-quarter global partial ----
    if (tid < 128) {
        float m = s_pm[0][tid]; int bi = s_pi[0][tid];
        #pragma unroll
        for (int w = 1; w < 4; w++) {
            float om = s_pm[w][tid]; int oi = s_pi[w][tid];
            if (om < m || (om == m && oi < bi)) { m = om; bi = oi; }
        }
        float l = 0.f, ssum = 0.f;
        #pragma unroll
        for (int w = 0; w < 4; w++) {
            float sc = __expf(m - s_pm[w][tid]);
            l    += s_pl[w][tid] * sc;
            ssum += s_ps[w][tid] * sc;
        }
        int n = row0 + tid;
        g_qm[qt][n] = m;
        g_ql[qt][n] = l;
        g_qs[qt][n] = ssum;
        g_qi[qt][n] = bi;
    }
}

// ---------------------------------------------------------------------------
// Merge the 4 quarter-partials; idx + loss partial + centroid gather.
// 16 points per block (grid 2048, 256 threads) for high occupancy.
// ---------------------------------------------------------------------------
__global__ __launch_bounds__(256)
void dkm_merge_kernel(const float* __restrict__ crep,
                      float* __restrict__ out_centroids,
                      float* __restrict__ out_idx)
{
    __shared__ int   s_idx[16];
    __shared__ float s_loss[16];
    const int tid = threadIdx.x;
    const int p0  = blockIdx.x * 16;

    if (tid < 16) {
        int n = p0 + tid;
        float m = g_qm[0][n]; int bi = g_qi[0][n];
        #pragma unroll
        for (int qq = 1; qq < 4; qq++) {
            float om = g_qm[qq][n];
            if (om < m) { m = om; bi = g_qi[qq][n]; }
        }
        float l = 0.f, ssum = 0.f;
        #pragma unroll
        for (int qq = 0; qq < 4; qq++) {
            float sc = __expf(m - g_qm[qq][n]);
            l    += g_ql[qq][n] * sc;
            ssum += g_qs[qq][n] * sc;
        }
        out_idx[n]  = (float)bi;
        s_idx[tid]  = bi;
        s_loss[tid] = ssum / l;
    }
    __syncthreads();
    if (tid == 0) {
        float a = 0.f;
        #pragma unroll
        for (int i = 0; i < 16; i++) a += s_loss[i];   // fixed order: deterministic
        g_lpart[blockIdx.x] = a;
    }

    // gather: 16 rows x 128 float4 = 2048 vec ops, 8 per thread
    for (int i = tid; i < 16 * (DIM / 4); i += 256) {
        int p = i >> 7, c4 = i & 127;
        int ci = s_idx[p];
        float4 v = *reinterpret_cast<const float4*>(crep + (size_t)ci * DIM + c4 * 4);
        *reinterpret_cast<float4*>(out_centroids + (size_t)(p0 + p) * DIM + c4 * 4) = v;
    }
}

// ---------------------------------------------------------------------------
// Final deterministic loss: fixed-order tree over the 2048 merge partials.
// ---------------------------------------------------------------------------
__global__ void loss_final_kernel(float* __restrict__ out_loss) {
    __shared__ float sm[1024];
    int tid = threadIdx.x;
    sm[tid] = g_lpart[tid] + g_lpart[tid + 1024];
    __syncthreads();
    #pragma unroll
    for (int o = 512; o > 0; o >>= 1) {
        if (tid < o) sm[tid] += sm[tid + o];
        __syncthreads();
    }
    if (tid == 0) out_loss[0] = sm[0] * (1.0f / (float)KCL);
}

// ---------------------------------------------------------------------------
extern "C" void kernel_launch(void* const* d_in, const int* in_sizes, int n_in,
                              void* d_out, int out_size) {
    const float* input = (const float*)d_in[0];   // [N, D]
    const float* crep  = (const float*)d_in[1];   // [K, D]

    float* out           = (float*)d_out;
    float* out_centroids = out;
    float* out_idx       = out + (size_t)N_PTS * DIM;
    float* out_loss      = out + (size_t)N_PTS * DIM + N_PTS;

    convert_b_kernel<<<(KCL * 32) / 256, 256>>>(crep);

    cudaFuncSetAttribute(dkm_gemm_kernel, cudaFuncAttributeMaxDynamicSharedMemorySize, DSMEM);
    dkm_gemm_kernel<<<(N_PTS / 128) * 4, 256, DSMEM>>>(input);

    dkm_merge_kernel<<<NMERGE, 256>>>(crep, out_centroids, out_idx);

    loss_final_kernel<<<1, 1024>>>(out_loss);
}

// round 13
// speedup vs baseline: 1.1957x; 1.0024x over previous
#include <cuda_runtime.h>
#include <cuda_fp16.h>
#include <stdint.h>
#include <math.h>

#define N_PTS 32768
#define DIM   512
#define KCL   1024

// ---------------- scratch (static device arrays: allocation-free) ----------
__device__ __half g_Bh[(size_t)KCL * DIM];     // 1 MB
__device__ __half g_Bl[(size_t)KCL * DIM];     // 1 MB
__device__ float g_cnorm[KCL];
// per-quarter softmax/argmin partials
__device__ float g_qm[4][N_PTS];
__device__ float g_ql[4][N_PTS];
__device__ float g_qs[4][N_PTS];
__device__ int   g_qi[4][N_PTS];
// per-merge-block loss partials
#define NMERGE 2048
__device__ float g_lpart[NMERGE];

// m16n8k16 fp16 MMA, fp32 accumulate, D=C
#define MMA_F16(d, a, b)                                                        \
    asm volatile(                                                               \
        "mma.sync.aligned.m16n8k16.row.col.f32.f16.f16.f32 "                    \
        "{%0,%1,%2,%3},{%4,%5,%6,%7},{%8,%9},{%0,%1,%2,%3};"                    \
        : "+f"((d)[0]), "+f"((d)[1]), "+f"((d)[2]), "+f"((d)[3])                \
        : "r"((a)[0]), "r"((a)[1]), "r"((a)[2]), "r"((a)[3]),                   \
          "r"((b)[0]), "r"((b)[1]))

#define LDMX4(r0, r1, r2, r3, addr)                                             \
    asm volatile("ldmatrix.sync.aligned.m8n8.x4.shared.b16 {%0,%1,%2,%3}, [%4];"\
                 : "=r"(r0), "=r"(r1), "=r"(r2), "=r"(r3) : "r"(addr))

#define CP_ASYNC16(dst, src)                                                    \
    asm volatile("cp.async.cg.shared.global [%0], [%1], 16;"                    \
                 :: "r"(dst), "l"(src) : "memory")
#define CP_COMMIT()  asm volatile("cp.async.commit_group;" ::: "memory")
#define CP_WAIT(n)   asm volatile("cp.async.wait_group %0;" :: "n"(n) : "memory")

#define SWZ(x) ((x) ^ (((x) >> 3) & 0x70))

__device__ __forceinline__ uint32_t smem_u32(const void* p) {
    uint32_t a;
    asm("{ .reg .u64 t; cvta.to.shared.u64 t, %1; cvt.u32.u64 %0, t; }" : "=r"(a) : "l"(p));
    return a;
}

// ---------------------------------------------------------------------------
// Convert crep fp32 rows -> fp16 (hi, lo) split + squared norms. Warp/row.
// (A is now split on-the-fly inside the GEMM kernel.)
// ---------------------------------------------------------------------------
__global__ void convert_b_kernel(const float* __restrict__ crep) {
    int warp = (blockIdx.x * blockDim.x + threadIdx.x) >> 5;
    int lane = threadIdx.x & 31;
    if (warp >= KCL) return;
    const float* row = crep + (size_t)warp * DIM;
    __half* hrow = g_Bh + (size_t)warp * DIM;
    __half* lrow = g_Bl + (size_t)warp * DIM;
    float sq = 0.f;
    #pragma unroll
    for (int i = 0; i < 4; i++) {
        int d = i * 128 + lane * 4;
        float4 v = *reinterpret_cast<const float4*>(row + d);
        float vv[4] = {v.x, v.y, v.z, v.w};
        __half hv[4], lv[4];
        #pragma unroll
        for (int q = 0; q < 4; q++) {
            float val = vv[q];
            sq = fmaf(val, val, sq);
            hv[q] = __float2half_rn(val);
            lv[q] = __float2half_rn(val - __half2float(hv[q]));
        }
        *reinterpret_cast<uint2*>(hrow + d) = *reinterpret_cast<uint2*>(hv);
        *reinterpret_cast<uint2*>(lrow + d) = *reinterpret_cast<uint2*>(lv);
    }
    #pragma unroll
    for (int o = 16; o > 0; o >>= 1) sq += __shfl_xor_sync(0xffffffffu, sq, o);
    if (lane == 0) g_cnorm[warp] = sq;
}

// ---------------------------------------------------------------------------
// GEMM kernel: one CTA = M-tile 128 x N-quarter 256, full K. grid = 1024.
// 3xFP16 mma.sync (hh+mh+hm), ldmatrix fragments, SW128 swizzle.
// B: 3-stage cp.async ring. A: fp32 loaded direct from input, split to
// hi/lo fp16 in registers (one stage ahead), stored to smem; row norms
// accumulated on the fly. Per-quarter partials to global.
// ---------------------------------------------------------------------------
#define STG_A   16384              // 128 rows * 128B
#define STG_B   32768              // 256 rows * 128B
#define STG_SZ  (STG_A + STG_B)    // 49152
#define NSTG    16                 // K = 512 / k32
#define DSMEM   (3 * STG_SZ)       // 147456

__global__ __launch_bounds__(256, 1)
void dkm_gemm_kernel(const float* __restrict__ input)
{
    extern __shared__ __align__(128) char dsm[];
    __shared__ float s_cn[256];
    __shared__ float s_xn[128];
    __shared__ float s_pm[4][128], s_pl[4][128], s_ps[4][128];
    __shared__ int   s_pi[4][128];

    const int tid  = threadIdx.x;
    const int wid  = tid >> 5;
    const int lane = tid & 31;
    const int q    = lane >> 2;
    const int kl   = lane & 3;
    const int g    = lane >> 3;        // ldmatrix address group
    const int lr   = lane & 7;
    const int wm   = wid & 1;          // M-tile (0..1) of 64 rows
    const int wn   = wid >> 1;         // N-tile (0..3) of 64 cols
    const int mt   = blockIdx.x >> 2;  // M-tile index (quarter fastest: A L2 reuse)
    const int qt   = blockIdx.x & 3;   // N-quarter
    const int row0 = mt * 128;
    const int c0   = qt * 256;
    const uint32_t dsmu = smem_u32(dsm);

    s_cn[tid] = g_cnorm[c0 + tid];

    // A loader thread mapping (fixed across stages): 4 chunks per thread
    const int ar = tid >> 3;           // row within block of 32 (offset it*32)
    const int ac = tid & 7;            // 4-float chunk (cols ac*4 .. ac*4+3)

    // ---- per-lane ldmatrix offsets (stage-independent) --------------------
    uint32_t offA[4], offB[4];
    #pragma unroll
    for (int mf = 0; mf < 4; mf++) {
        int r = wm * 64 + mf * 16 + (g & 1) * 8 + lr;
        offA[mf] = (uint32_t)(r * 128) + ((uint32_t)((g >> 1) * 16) ^ ((uint32_t)(r & 7) << 4));
    }
    #pragma unroll
    for (int t = 0; t < 4; t++) {
        int r = wn * 64 + t * 16 + (g >= 2 ? 8 : 0) + lr;
        offB[t] = (uint32_t)(r * 128) + ((uint32_t)((g & 1) * 16) ^ ((uint32_t)(r & 7) << 4));
    }

    // ---- B stage loader: 2048 x 16B chunks, 8 per thread ------------------
    auto load_B = [&](int s) {
        const int k0 = s * 32;
        const uint32_t base = dsmu + (s % 3) * STG_SZ + STG_A;
        #pragma unroll
        for (int it = 0; it < 8; it++) {
            int i = it * 256 + tid;
            int r = i >> 3, c = i & 7;
            const __half* src =
                (c < 4 ? g_Bh + (size_t)(c0 + r) * DIM + k0 + c * 8
                       : g_Bl + (size_t)(c0 + r) * DIM + k0 + (c - 4) * 8);
            CP_ASYNC16(base + SWZ((uint32_t)(r * 128 + c * 16)), (const void*)src);
        }
        CP_COMMIT();
    };

    // ---- A: fp32 prefetch (one stage ahead) + convert/store ---------------
    float4 aPre[4];
    float  ns[4] = {0.f, 0.f, 0.f, 0.f};
    auto load_A = [&](int s) {
        const int k0 = s * 32;
        #pragma unroll
        for (int it = 0; it < 4; it++) {
            int r = it * 32 + ar;
            aPre[it] = *reinterpret_cast<const float4*>(
                &input[(size_t)(row0 + r) * DIM + k0 + ac * 4]);
        }
    };
    auto store_A = [&](int s) {
        const int sb = (s % 3) * STG_SZ;
        #pragma unroll
        for (int it = 0; it < 4; it++) {
            int r = it * 32 + ar;
            float v[4] = {aPre[it].x, aPre[it].y, aPre[it].z, aPre[it].w};
            __half hv[4], lv[4];
            #pragma unroll
            for (int u = 0; u < 4; u++) {
                ns[it] = fmaf(v[u], v[u], ns[it]);
                hv[u] = __float2half_rn(v[u]);
                lv[u] = __float2half_rn(v[u] - __half2float(hv[u]));
            }
            *reinterpret_cast<uint2*>(dsm + sb + SWZ((uint32_t)(r * 128 + ac * 8))) =
                *reinterpret_cast<uint2*>(hv);
            *reinterpret_cast<uint2*>(dsm + sb + SWZ((uint32_t)(r * 128 + 64 + ac * 8))) =
                *reinterpret_cast<uint2*>(lv);
        }
    };

    float acc[4][8][4];
    #pragma unroll
    for (int mf = 0; mf < 4; mf++)
        #pragma unroll
        for (int nf = 0; nf < 8; nf++)
            #pragma unroll
            for (int t = 0; t < 4; t++) acc[mf][nf][t] = 0.f;

    load_B(0);
    load_B(1);
    load_A(0);

    for (int s = 0; s < NSTG; s++) {
        if (s < NSTG - 2) { CP_WAIT(1); } else { CP_WAIT(0); }
        store_A(s);                       // stage-s A region: last read at s-3
        __syncthreads();
        if (s + 2 < NSTG) load_B(s + 2);  // overlaps with compute below
        if (s + 1 < NSTG) load_A(s + 1);

        const uint32_t abase = dsmu + (s % 3) * STG_SZ;
        const uint32_t bbase = abase + STG_A;

        #pragma unroll
        for (int kb = 0; kb < 2; kb++) {           // two k16 steps per stage
            const uint32_t kx = (uint32_t)kb << 5;
            uint32_t ah[4][4], am[4][4], bb[4][4];
            #pragma unroll
            for (int mf = 0; mf < 4; mf++) {
                const uint32_t aH = abase + (offA[mf] ^ kx);
                LDMX4(ah[mf][0], ah[mf][1], ah[mf][2], ah[mf][3], aH);
                LDMX4(am[mf][0], am[mf][1], am[mf][2], am[mf][3], aH ^ 64u);
            }
            // B hi fragments -> passes hh and mh
            #pragma unroll
            for (int t = 0; t < 4; t++)
                LDMX4(bb[t][0], bb[t][1], bb[t][2], bb[t][3], bbase + (offB[t] ^ kx));
            #pragma unroll
            for (int mf = 0; mf < 4; mf++)
                #pragma unroll
                for (int t = 0; t < 4; t++) {
                    MMA_F16(acc[mf][2 * t],     ah[mf], (bb[t] + 0));
                    MMA_F16(acc[mf][2 * t + 1], ah[mf], (bb[t] + 2));
                }
            #pragma unroll
            for (int mf = 0; mf < 4; mf++)
                #pragma unroll
                for (int t = 0; t < 4; t++) {
                    MMA_F16(acc[mf][2 * t],     am[mf], (bb[t] + 0));
                    MMA_F16(acc[mf][2 * t + 1], am[mf], (bb[t] + 2));
                }
            // B lo fragments -> pass hm
            #pragma unroll
            for (int t = 0; t < 4; t++)
                LDMX4(bb[t][0], bb[t][1], bb[t][2], bb[t][3], bbase + ((offB[t] ^ kx) ^ 64u));
            #pragma unroll
            for (int mf = 0; mf < 4; mf++)
                #pragma unroll
                for (int t = 0; t < 4; t++) {
                    MMA_F16(acc[mf][2 * t],     ah[mf], (bb[t] + 0));
                    MMA_F16(acc[mf][2 * t + 1], ah[mf], (bb[t] + 2));
                }
        }
    }

    // ---- publish row norms (8 threads share each row) ---------------------
    #pragma unroll
    for (int it = 0; it < 4; it++) {
        float v = ns[it];
        v += __shfl_xor_sync(0xffffffffu, v, 1);
        v += __shfl_xor_sync(0xffffffffu, v, 2);
        v += __shfl_xor_sync(0xffffffffu, v, 4);
        if ((tid & 7) == 0) s_xn[it * 32 + ar] = v;
    }
    __syncthreads();

    // ---- single epilogue: softmax/argmin over this quarter ----------------
    #pragma unroll
    for (int mf = 0; mf < 4; mf++) {
        #pragma unroll
        for (int j = 0; j < 2; j++) {
            const int rloc = wm * 64 + mf * 16 + j * 8 + q;
            const float xn = s_xn[rloc];
            float d2v[16];
            float bmn = 3.4e38f; int ba = 0;
            #pragma unroll
            for (int nf = 0; nf < 8; nf++) {
                #pragma unroll
                for (int t = 0; t < 2; t++) {
                    int col = c0 + wn * 64 + nf * 8 + 2 * kl + t;
                    float d2 = xn + s_cn[col - c0] - 2.f * acc[mf][nf][j * 2 + t];
                    d2v[nf * 2 + t] = d2;
                    if (d2 < bmn || (d2 == bmn && col < ba)) { bmn = d2; ba = col; }
                }
            }
            #pragma unroll
            for (int o = 1; o <= 2; o <<= 1) {
                float om = __shfl_xor_sync(0xffffffffu, bmn, o);
                int   oa = __shfl_xor_sync(0xffffffffu, ba, o);
                if (om < bmn || (om == bmn && oa < ba)) { bmn = om; ba = oa; }
            }
            float le = 0.f, se = 0.f;
            #pragma unroll
            for (int v = 0; v < 16; v++) {
                float w = __expf(bmn - d2v[v]);
                le += w;
                se = fmaf(w, d2v[v], se);
            }
            #pragma unroll
            for (int o = 1; o <= 2; o <<= 1) {
                le += __shfl_xor_sync(0xffffffffu, le, o);
                se += __shfl_xor_sync(0xffffffffu, se, o);
            }
            if (kl == 0) {
                s_pm[wn][rloc] = bmn;
                s_pl[wn][rloc] = le;
                s_ps[wn][rloc] = se;
                s_pi[wn][rloc] = ba;
            }
        }
    }
    __syncthreads();

    // ---- merge the 4 N-warp partials; write per-quarter global partial ----
    if (tid < 128) {
        float m = s_pm[0][tid]; int bi = s_pi[0][tid];
        #pragma unroll
        for (int w = 1; w < 4; w++) {
            float om = s_pm[w][tid]; int oi = s_pi[w][tid];
            if (om < m || (om == m && oi < bi)) { m = om; bi = oi; }
        }
        float l = 0.f, ssum = 0.f;
        #pragma unroll
        for (int w = 0; w < 4; w++) {
            float sc = __expf(m - s_pm[w][tid]);
            l    += s_pl[w][tid] * sc;
            ssum += s_ps[w][tid] * sc;
        }
        int n = row0 + tid;
        g_qm[qt][n] = m;
        g_ql[qt][n] = l;
        g_qs[qt][n] = ssum;
        g_qi[qt][n] = bi;
    }
}

// ---------------------------------------------------------------------------
// Merge the 4 quarter-partials; idx + loss partial + centroid gather.
// 16 points per block (grid 2048, 256 threads) for high occupancy.
// ---------------------------------------------------------------------------
__global__ __launch_bounds__(256)
void dkm_merge_kernel(const float* __restrict__ crep,
                      float* __restrict__ out_centroids,
                      float* __restrict__ out_idx)
{
    __shared__ int   s_idx[16];
    __shared__ float s_loss[16];
    const int tid = threadIdx.x;
    const int p0  = blockIdx.x * 16;

    if (tid < 16) {
        int n = p0 + tid;
        float m = g_qm[0][n]; int bi = g_qi[0][n];
        #pragma unroll
        for (int qq = 1; qq < 4; qq++) {
            float om = g_qm[qq][n];
            if (om < m) { m = om; bi = g_qi[qq][n]; }
        }
        float l = 0.f, ssum = 0.f;
        #pragma unroll
        for (int qq = 0; qq < 4; qq++) {
            float sc = __expf(m - g_qm[qq][n]);
            l    += g_ql[qq][n] * sc;
            ssum += g_qs[qq][n] * sc;
        }
        out_idx[n]  = (float)bi;
        s_idx[tid]  = bi;
        s_loss[tid] = ssum / l;
    }
    __syncthreads();
    if (tid == 0) {
        float a = 0.f;
        #pragma unroll
        for (int i = 0; i < 16; i++) a += s_loss[i];   // fixed order: deterministic
        g_lpart[blockIdx.x] = a;
    }

    // gather: 16 rows x 128 float4 = 2048 vec ops, 8 per thread
    for (int i = tid; i < 16 * (DIM / 4); i += 256) {
        int p = i >> 7, c4 = i & 127;
        int ci = s_idx[p];
        float4 v = *reinterpret_cast<const float4*>(crep + (size_t)ci * DIM + c4 * 4);
        *reinterpret_cast<float4*>(out_centroids + (size_t)(p0 + p) * DIM + c4 * 4) = v;
    }
}

// ---------------------------------------------------------------------------
// Final deterministic loss: fixed-order tree over the 2048 merge partials.
// ---------------------------------------------------------------------------
__global__ void loss_final_kernel(float* __restrict__ out_loss) {
    __shared__ float sm[1024];
    int tid = threadIdx.x;
    sm[tid] = g_lpart[tid] + g_lpart[tid + 1024];
    __syncthreads();
    #pragma unroll
    for (int o = 512; o > 0; o >>= 1) {
        if (tid < o) sm[tid] += sm[tid + o];
        __syncthreads();
    }
    if (tid == 0) out_loss[0] = sm[0] * (1.0f / (float)KCL);
}

// ---------------------------------------------------------------------------
extern "C" void kernel_launch(void* const* d_in, const int* in_sizes, int n_in,
                              void* d_out, int out_size) {
    const float* input = (const float*)d_in[0];   // [N, D]
    const float* crep  = (const float*)d_in[1];   // [K, D]

    float* out           = (float*)d_out;
    float* out_centroids = out;
    float* out_idx       = out + (size_t)N_PTS * DIM;
    float* out_loss      = out + (size_t)N_PTS * DIM + N_PTS;

    convert_b_kernel<<<(KCL * 32) / 256, 256>>>(crep);

    cudaFuncSetAttribute(dkm_gemm_kernel, cudaFuncAttributeMaxDynamicSharedMemorySize, DSMEM);
    dkm_gemm_kernel<<<(N_PTS / 128) * 4, 256, DSMEM>>>(input);

    dkm_merge_kernel<<<NMERGE, 256>>>(crep, out_centroids, out_idx);

    loss_final_kernel<<<1, 1024>>>(out_loss);
}

// round 14
// speedup vs baseline: 1.1958x; 1.0001x over previous
#include <cuda_runtime.h>
#include <cuda_fp16.h>
#include <stdint.h>
#include <math.h>

#define N_PTS 32768
#define DIM   512
#define KCL   1024

// ---------------- scratch (static device arrays: allocation-free) ----------
__device__ __half g_Bh[(size_t)KCL * DIM];     // 1 MB
__device__ __half g_Bl[(size_t)KCL * DIM];     // 1 MB
__device__ float g_cnorm[KCL];
// per-quarter softmax/argmin partials
__device__ float g_qm[4][N_PTS];
__device__ float g_ql[4][N_PTS];
__device__ float g_qs[4][N_PTS];
__device__ int   g_qi[4][N_PTS];
// per-merge-block loss partials
#define NMERGE 2048
__device__ float g_lpart[NMERGE];

// m16n8k16 fp16 MMA, fp32 accumulate, D=C
#define MMA_F16(d, a, b)                                                        \
    asm volatile(                                                               \
        "mma.sync.aligned.m16n8k16.row.col.f32.f16.f16.f32 "                    \
        "{%0,%1,%2,%3},{%4,%5,%6,%7},{%8,%9},{%0,%1,%2,%3};"                    \
        : "+f"((d)[0]), "+f"((d)[1]), "+f"((d)[2]), "+f"((d)[3])                \
        : "r"((a)[0]), "r"((a)[1]), "r"((a)[2]), "r"((a)[3]),                   \
          "r"((b)[0]), "r"((b)[1]))

#define LDMX4(r0, r1, r2, r3, addr)                                             \
    asm volatile("ldmatrix.sync.aligned.m8n8.x4.shared.b16 {%0,%1,%2,%3}, [%4];"\
                 : "=r"(r0), "=r"(r1), "=r"(r2), "=r"(r3) : "r"(addr))

#define CP_ASYNC16(dst, src)                                                    \
    asm volatile("cp.async.cg.shared.global [%0], [%1], 16;"                    \
                 :: "r"(dst), "l"(src) : "memory")
#define CP_COMMIT()  asm volatile("cp.async.commit_group;" ::: "memory")
#define CP_WAIT(n)   asm volatile("cp.async.wait_group %0;" :: "n"(n) : "memory")

#define SWZ(x) ((x) ^ (((x) >> 3) & 0x70))

__device__ __forceinline__ uint32_t smem_u32(const void* p) {
    uint32_t a;
    asm("{ .reg .u64 t; cvta.to.shared.u64 t, %1; cvt.u32.u64 %0, t; }" : "=r"(a) : "l"(p));
    return a;
}

// ---------------------------------------------------------------------------
// Convert crep fp32 rows -> fp16 (hi, lo) split + squared norms. Warp/row.
// (A is now split on-the-fly inside the GEMM kernel.)
// ---------------------------------------------------------------------------
__global__ void convert_b_kernel(const float* __restrict__ crep) {
    int warp = (blockIdx.x * blockDim.x + threadIdx.x) >> 5;
    int lane = threadIdx.x & 31;
    if (warp >= KCL) return;
    const float* row = crep + (size_t)warp * DIM;
    __half* hrow = g_Bh + (size_t)warp * DIM;
    __half* lrow = g_Bl + (size_t)warp * DIM;
    float sq = 0.f;
    #pragma unroll
    for (int i = 0; i < 4; i++) {
        int d = i * 128 + lane * 4;
        float4 v = *reinterpret_cast<const float4*>(row + d);
        float vv[4] = {v.x, v.y, v.z, v.w};
        __half hv[4], lv[4];
        #pragma unroll
        for (int q = 0; q < 4; q++) {
            float val = vv[q];
            sq = fmaf(val, val, sq);
            hv[q] = __float2half_rn(val);
            lv[q] = __float2half_rn(val - __half2float(hv[q]));
        }
        *reinterpret_cast<uint2*>(hrow + d) = *reinterpret_cast<uint2*>(hv);
        *reinterpret_cast<uint2*>(lrow + d) = *reinterpret_cast<uint2*>(lv);
    }
    #pragma unroll
    for (int o = 16; o > 0; o >>= 1) sq += __shfl_xor_sync(0xffffffffu, sq, o);
    if (lane == 0) g_cnorm[warp] = sq;
}

// ---------------------------------------------------------------------------
// GEMM kernel: one CTA = M-tile 128 x N-quarter 256, full K. grid = 1024.
// 3xFP16 mma.sync (hh+mh+hm), ldmatrix fragments, SW128 swizzle.
// B: 3-stage cp.async ring. A: fp32 loaded direct from input, split to
// hi/lo fp16 in registers (one stage ahead), stored to smem; row norms
// accumulated on the fly. Per-quarter partials to global.
// ---------------------------------------------------------------------------
#define STG_A   16384              // 128 rows * 128B
#define STG_B   32768              // 256 rows * 128B
#define STG_SZ  (STG_A + STG_B)    // 49152
#define NSTG    16                 // K = 512 / k32
#define DSMEM   (3 * STG_SZ)       // 147456

__global__ __launch_bounds__(256, 1)
void dkm_gemm_kernel(const float* __restrict__ input)
{
    extern __shared__ __align__(128) char dsm[];
    __shared__ float s_cn[256];
    __shared__ float s_xn[128];
    __shared__ float s_pm[4][128], s_pl[4][128], s_ps[4][128];
    __shared__ int   s_pi[4][128];

    const int tid  = threadIdx.x;
    const int wid  = tid >> 5;
    const int lane = tid & 31;
    const int q    = lane >> 2;
    const int kl   = lane & 3;
    const int g    = lane >> 3;        // ldmatrix address group
    const int lr   = lane & 7;
    const int wm   = wid & 1;          // M-tile (0..1) of 64 rows
    const int wn   = wid >> 1;         // N-tile (0..3) of 64 cols
    const int mt   = blockIdx.x >> 2;  // M-tile index (quarter fastest: A L2 reuse)
    const int qt   = blockIdx.x & 3;   // N-quarter
    const int row0 = mt * 128;
    const int c0   = qt * 256;
    const uint32_t dsmu = smem_u32(dsm);

    s_cn[tid] = g_cnorm[c0 + tid];

    // A loader thread mapping (fixed across stages): 4 chunks per thread
    const int ar = tid >> 3;           // row within block of 32 (offset it*32)
    const int ac = tid & 7;            // 4-float chunk (cols ac*4 .. ac*4+3)

    // ---- per-lane ldmatrix offsets (stage-independent) --------------------
    uint32_t offA[4], offB[4];
    #pragma unroll
    for (int mf = 0; mf < 4; mf++) {
        int r = wm * 64 + mf * 16 + (g & 1) * 8 + lr;
        offA[mf] = (uint32_t)(r * 128) + ((uint32_t)((g >> 1) * 16) ^ ((uint32_t)(r & 7) << 4));
    }
    #pragma unroll
    for (int t = 0; t < 4; t++) {
        int r = wn * 64 + t * 16 + (g >= 2 ? 8 : 0) + lr;
        offB[t] = (uint32_t)(r * 128) + ((uint32_t)((g & 1) * 16) ^ ((uint32_t)(r & 7) << 4));
    }

    // ---- B stage loader: 2048 x 16B chunks, 8 per thread ------------------
    auto load_B = [&](int s) {
        const int k0 = s * 32;
        const uint32_t base = dsmu + (s % 3) * STG_SZ + STG_A;
        #pragma unroll
        for (int it = 0; it < 8; it++) {
            int i = it * 256 + tid;
            int r = i >> 3, c = i & 7;
            const __half* src =
                (c < 4 ? g_Bh + (size_t)(c0 + r) * DIM + k0 + c * 8
                       : g_Bl + (size_t)(c0 + r) * DIM + k0 + (c - 4) * 8);
            CP_ASYNC16(base + SWZ((uint32_t)(r * 128 + c * 16)), (const void*)src);
        }
        CP_COMMIT();
    };

    // ---- A: fp32 prefetch (one stage ahead) + convert/store ---------------
    float4 aPre[4];
    float  ns[4] = {0.f, 0.f, 0.f, 0.f};
    auto load_A = [&](int s) {
        const int k0 = s * 32;
        #pragma unroll
        for (int it = 0; it < 4; it++) {
            int r = it * 32 + ar;
            aPre[it] = *reinterpret_cast<const float4*>(
                &input[(size_t)(row0 + r) * DIM + k0 + ac * 4]);
        }
    };
    auto store_A = [&](int s) {
        const int sb = (s % 3) * STG_SZ;
        #pragma unroll
        for (int it = 0; it < 4; it++) {
            int r = it * 32 + ar;
            float v[4] = {aPre[it].x, aPre[it].y, aPre[it].z, aPre[it].w};
            __half hv[4], lv[4];
            #pragma unroll
            for (int u = 0; u < 4; u++) {
                ns[it] = fmaf(v[u], v[u], ns[it]);
                hv[u] = __float2half_rn(v[u]);
                lv[u] = __float2half_rn(v[u] - __half2float(hv[u]));
            }
            *reinterpret_cast<uint2*>(dsm + sb + SWZ((uint32_t)(r * 128 + ac * 8))) =
                *reinterpret_cast<uint2*>(hv);
            *reinterpret_cast<uint2*>(dsm + sb + SWZ((uint32_t)(r * 128 + 64 + ac * 8))) =
                *reinterpret_cast<uint2*>(lv);
        }
    };

    float acc[4][8][4];
    #pragma unroll
    for (int mf = 0; mf < 4; mf++)
        #pragma unroll
        for (int nf = 0; nf < 8; nf++)
            #pragma unroll
            for (int t = 0; t < 4; t++) acc[mf][nf][t] = 0.f;

    load_B(0);
    load_B(1);
    load_A(0);

    for (int s = 0; s < NSTG; s++) {
        if (s < NSTG - 2) { CP_WAIT(1); } else { CP_WAIT(0); }
        store_A(s);                       // stage-s A region: last read at s-3
        __syncthreads();
        if (s + 2 < NSTG) load_B(s + 2);  // overlaps with compute below
        if (s + 1 < NSTG) load_A(s + 1);

        const uint32_t abase = dsmu + (s % 3) * STG_SZ;
        const uint32_t bbase = abase + STG_A;

        #pragma unroll
        for (int kb = 0; kb < 2; kb++) {           // two k16 steps per stage
            const uint32_t kx = (uint32_t)kb << 5;
            uint32_t ah[4][4], am[4][4], bb[4][4];
            #pragma unroll
            for (int mf = 0; mf < 4; mf++) {
                const uint32_t aH = abase + (offA[mf] ^ kx);
                LDMX4(ah[mf][0], ah[mf][1], ah[mf][2], ah[mf][3], aH);
                LDMX4(am[mf][0], am[mf][1], am[mf][2], am[mf][3], aH ^ 64u);
            }
            // B hi fragments -> passes hh and mh
            #pragma unroll
            for (int t = 0; t < 4; t++)
                LDMX4(bb[t][0], bb[t][1], bb[t][2], bb[t][3], bbase + (offB[t] ^ kx));
            #pragma unroll
            for (int mf = 0; mf < 4; mf++)
                #pragma unroll
                for (int t = 0; t < 4; t++) {
                    MMA_F16(acc[mf][2 * t],     ah[mf], (bb[t] + 0));
                    MMA_F16(acc[mf][2 * t + 1], ah[mf], (bb[t] + 2));
                }
            #pragma unroll
            for (int mf = 0; mf < 4; mf++)
                #pragma unroll
                for (int t = 0; t < 4; t++) {
                    MMA_F16(acc[mf][2 * t],     am[mf], (bb[t] + 0));
                    MMA_F16(acc[mf][2 * t + 1], am[mf], (bb[t] + 2));
                }
            // B lo fragments -> pass hm
            #pragma unroll
            for (int t = 0; t < 4; t++)
                LDMX4(bb[t][0], bb[t][1], bb[t][2], bb[t][3], bbase + ((offB[t] ^ kx) ^ 64u));
            #pragma unroll
            for (int mf = 0; mf < 4; mf++)
                #pragma unroll
                for (int t = 0; t < 4; t++) {
                    MMA_F16(acc[mf][2 * t],     ah[mf], (bb[t] + 0));
                    MMA_F16(acc[mf][2 * t + 1], ah[mf], (bb[t] + 2));
                }
        }
    }

    // ---- publish row norms (8 threads share each row) ---------------------
    #pragma unroll
    for (int it = 0; it < 4; it++) {
        float v = ns[it];
        v += __shfl_xor_sync(0xffffffffu, v, 1);
        v += __shfl_xor_sync(0xffffffffu, v, 2);
        v += __shfl_xor_sync(0xffffffffu, v, 4);
        if ((tid & 7) == 0) s_xn[it * 32 + ar] = v;
    }
    __syncthreads();

    // ---- single epilogue: softmax/argmin over this quarter ----------------
    #pragma unroll
    for (int mf = 0; mf < 4; mf++) {
        #pragma unroll
        for (int j = 0; j < 2; j++) {
            const int rloc = wm * 64 + mf * 16 + j * 8 + q;
            const float xn = s_xn[rloc];
            float d2v[16];
            float bmn = 3.4e38f; int ba = 0;
            #pragma unroll
            for (int nf = 0; nf < 8; nf++) {
                #pragma unroll
                for (int t = 0; t < 2; t++) {
                    int col = c0 + wn * 64 + nf * 8 + 2 * kl + t;
                    float d2 = xn + s_cn[col - c0] - 2.f * acc[mf][nf][j * 2 + t];
                    d2v[nf * 2 + t] = d2;
                    if (d2 < bmn || (d2 == bmn && col < ba)) { bmn = d2; ba = col; }
                }
            }
            #pragma unroll
            for (int o = 1; o <= 2; o <<= 1) {
                float om = __shfl_xor_sync(0xffffffffu, bmn, o);
                int   oa = __shfl_xor_sync(0xffffffffu, ba, o);
                if (om < bmn || (om == bmn && oa < ba)) { bmn = om; ba = oa; }
            }
            float le = 0.f, se = 0.f;
            #pragma unroll
            for (int v = 0; v < 16; v++) {
                float w = __expf(bmn - d2v[v]);
                le += w;
                se = fmaf(w, d2v[v], se);
            }
            #pragma unroll
            for (int o = 1; o <= 2; o <<= 1) {
                le += __shfl_xor_sync(0xffffffffu, le, o);
                se += __shfl_xor_sync(0xffffffffu, se, o);
            }
            if (kl == 0) {
                s_pm[wn][rloc] = bmn;
                s_pl[wn][rloc] = le;
                s_ps[wn][rloc] = se;
                s_pi[wn][rloc] = ba;
            }
        }
    }
    __syncthreads();

    // ---- merge the 4 N-warp partials; write per-quarter global partial ----
    if (tid < 128) {
        float m = s_pm[0][tid]; int bi = s_pi[0][tid];
        #pragma unroll
        for (int w = 1; w < 4; w++) {
            float om = s_pm[w][tid]; int oi = s_pi[w][tid];
            if (om < m || (om == m && oi < bi)) { m = om; bi = oi; }
        }
        float l = 0.f, ssum = 0.f;
        #pragma unroll
        for (int w = 0; w < 4; w++) {
            float sc = __expf(m - s_pm[w][tid]);
            l    += s_pl[w][tid] * sc;
            ssum += s_ps[w][tid] * sc;
        }
        int n = row0 + tid;
        g_qm[qt][n] = m;
        g_ql[qt][n] = l;
        g_qs[qt][n] = ssum;
        g_qi[qt][n] = bi;
    }
}

// ---------------------------------------------------------------------------
// Merge the 4 quarter-partials; idx + loss partial + centroid gather.
// 16 points per block (grid 2048, 256 threads) for high occupancy.
// ---------------------------------------------------------------------------
__global__ __launch_bounds__(256)
void dkm_merge_kernel(const float* __restrict__ crep,
                      float* __restrict__ out_centroids,
                      float* __restrict__ out_idx)
{
    __shared__ int   s_idx[16];
    __shared__ float s_loss[16];
    const int tid = threadIdx.x;
    const int p0  = blockIdx.x * 16;

    if (tid < 16) {
        int n = p0 + tid;
        float m = g_qm[0][n]; int bi = g_qi[0][n];
        #pragma unroll
        for (int qq = 1; qq < 4; qq++) {
            float om = g_qm[qq][n];
            if (om < m) { m = om; bi = g_qi[qq][n]; }
        }
        float l = 0.f, ssum = 0.f;
        #pragma unroll
        for (int qq = 0; qq < 4; qq++) {
            float sc = __expf(m - g_qm[qq][n]);
            l    += g_ql[qq][n] * sc;
            ssum += g_qs[qq][n] * sc;
        }
        out_idx[n]  = (float)bi;
        s_idx[tid]  = bi;
        s_loss[tid] = ssum / l;
    }
    __syncthreads();
    if (tid == 0) {
        float a = 0.f;
        #pragma unroll
        for (int i = 0; i < 16; i++) a += s_loss[i];   // fixed order: deterministic
        g_lpart[blockIdx.x] = a;
    }

    // gather: 16 rows x 128 float4 = 2048 vec ops, 8 per thread
    for (int i = tid; i < 16 * (DIM / 4); i += 256) {
        int p = i >> 7, c4 = i & 127;
        int ci = s_idx[p];
        float4 v = *reinterpret_cast<const float4*>(crep + (size_t)ci * DIM + c4 * 4);
        *reinterpret_cast<float4*>(out_centroids + (size_t)(p0 + p) * DIM + c4 * 4) = v;
    }
}

// ---------------------------------------------------------------------------
// Final deterministic loss: fixed-order tree over the 2048 merge partials.
// ---------------------------------------------------------------------------
__global__ void loss_final_kernel(float* __restrict__ out_loss) {
    __shared__ float sm[1024];
    int tid = threadIdx.x;
    sm[tid] = g_lpart[tid] + g_lpart[tid + 1024];
    __syncthreads();
    #pragma unroll
    for (int o = 512; o > 0; o >>= 1) {
        if (tid < o) sm[tid] += sm[tid + o];
        __syncthreads();
    }
    if (tid == 0) out_loss[0] = sm[0] * (1.0f / (float)KCL);
}

// ---------------------------------------------------------------------------
extern "C" void kernel_launch(void* const* d_in, const int* in_sizes, int n_in,
                              void* d_out, int out_size) {
    const float* input = (const float*)d_in[0];   // [N, D]
    const float* crep  = (const float*)d_in[1];   // [K, D]

    float* out           = (float*)d_out;
    float* out_centroids = out;
    float* out_idx       = out + (size_t)N_PTS * DIM;
    float* out_loss      = out + (size_t)N_PTS * DIM + N_PTS;

    convert_b_kernel<<<(KCL * 32) / 256, 256>>>(crep);

    cudaFuncSetAttribute(dkm_gemm_kernel, cudaFuncAttributeMaxDynamicSharedMemorySize, DSMEM);
    dkm_gemm_kernel<<<(N_PTS / 128) * 4, 256, DSMEM>>>(input);

    dkm_merge_kernel<<<NMERGE, 256>>>(crep, out_centroids, out_idx);

    loss_final_kernel<<<1, 1024>>>(out_loss);
}